// round 4
// baseline (speedup 1.0000x reference)
#include <cuda_runtime.h>
#include <cuda_bf16.h>
#include <cstdint>

// (B, Sq, Sk, d, dv) = (8, 2048, 2048, 512, 512), fp32.
#define BATCH 8
#define SEQ   2048
#define DIM   512

// Scratch for M = K^T V : 8 * 512 * 512 floats = 8 MiB
__device__ float g_M[BATCH * DIM * DIM];
// valid_len dtype flag: 1 if int64, 0 if int32 (detected at runtime)
__device__ int g_vlen_is64;

// ---------------------------------------------------------------------------
// Detector: if valid_len is truly int64, every 8-byte word in the first 8KB
// is a value in [0, 512). If it's int32 data, word q = v[2q] + v[2q+1]*2^32,
// which is >= 2^32 whenever v[2q+1] != 0 (near-certain across 1024 words).
// Reads only 8KB = safe under both dtype hypotheses.
// ---------------------------------------------------------------------------
__global__ void detect_vlen_kernel(const unsigned long long* __restrict__ v) {
    __shared__ int bad;
    if (threadIdx.x == 0) bad = 0;
    __syncthreads();
    for (int i = threadIdx.x; i < 1024; i += blockDim.x) {
        unsigned long long x = v[i];
        if (x >= 512ull) atomicOr(&bad, 1);
    }
    __syncthreads();
    if (threadIdx.x == 0) g_vlen_is64 = bad ? 0 : 1;
}

// ---------------------------------------------------------------------------
// Kernel A: M[b] = K[b]^T @ V[b]
// ---------------------------------------------------------------------------
__global__ __launch_bounds__(256) void ktv_kernel(const float* __restrict__ K,
                                                  const float* __restrict__ V) {
    const int b  = blockIdx.z;
    const int i0 = blockIdx.y * 128;
    const int j0 = blockIdx.x * 128;
    const float* Kb = K + (size_t)b * SEQ * DIM;
    const float* Vb = V + (size_t)b * SEQ * DIM;
    float* Mb = g_M + (size_t)b * DIM * DIM;

    __shared__ float As[8][128];
    __shared__ float Bs[8][128];

    const int t = threadIdx.x;
    const int loadRow = t >> 5;
    const int loadCol = (t & 31) << 2;
    const int tx = t & 15;
    const int ty = t >> 4;

    float acc[8][8] = {};
    float ar[8], br[8];

    for (int k0 = 0; k0 < SEQ; k0 += 8) {
        *(float4*)&As[loadRow][loadCol] =
            *(const float4*)&Kb[(size_t)(k0 + loadRow) * DIM + i0 + loadCol];
        *(float4*)&Bs[loadRow][loadCol] =
            *(const float4*)&Vb[(size_t)(k0 + loadRow) * DIM + j0 + loadCol];
        __syncthreads();
#pragma unroll
        for (int kk = 0; kk < 8; kk++) {
            *(float4*)&ar[0] = *(float4*)&As[kk][ty * 4];
            *(float4*)&ar[4] = *(float4*)&As[kk][64 + ty * 4];
            *(float4*)&br[0] = *(float4*)&Bs[kk][tx * 4];
            *(float4*)&br[4] = *(float4*)&Bs[kk][64 + tx * 4];
#pragma unroll
            for (int ii = 0; ii < 8; ii++)
#pragma unroll
                for (int jj = 0; jj < 8; jj++)
                    acc[ii][jj] += ar[ii] * br[jj];
        }
        __syncthreads();
    }

#pragma unroll
    for (int ii = 0; ii < 8; ii++) {
        const int i = i0 + ((ii < 4) ? (ty * 4 + ii) : (64 + ty * 4 + ii - 4));
        float4 v0 = make_float4(acc[ii][0], acc[ii][1], acc[ii][2], acc[ii][3]);
        float4 v1 = make_float4(acc[ii][4], acc[ii][5], acc[ii][6], acc[ii][7]);
        *(float4*)&Mb[(size_t)i * DIM + j0 + tx * 4]      = v0;
        *(float4*)&Mb[(size_t)i * DIM + j0 + 64 + tx * 4] = v1;
    }
}

// ---------------------------------------------------------------------------
// Kernel B: X[b] = Q[b] @ M[b] * (1/sqrt(512)) -> logits into d_out
// ---------------------------------------------------------------------------
__global__ __launch_bounds__(256) void qm_kernel(const float* __restrict__ Q,
                                                 float* __restrict__ X) {
    const int b  = blockIdx.z;
    const int i0 = blockIdx.y * 128;
    const int j0 = blockIdx.x * 128;
    const float* Qb = Q + (size_t)b * SEQ * DIM;
    const float* Mb = g_M + (size_t)b * DIM * DIM;
    float* Xb = X + (size_t)b * SEQ * DIM;

    __shared__ float As[8][132];
    __shared__ float Bs[8][128];

    const int t = threadIdx.x;
    const int aRow = t >> 1;
    const int aCol = (t & 1) << 2;
    const int loadRow = t >> 5;
    const int loadCol = (t & 31) << 2;
    const int tx = t & 15;
    const int ty = t >> 4;

    float acc[8][8] = {};
    float ar[8], br[8];

    for (int k0 = 0; k0 < DIM; k0 += 8) {
        float4 a4 = *(const float4*)&Qb[(size_t)(i0 + aRow) * DIM + k0 + aCol];
        As[aCol + 0][aRow] = a4.x;
        As[aCol + 1][aRow] = a4.y;
        As[aCol + 2][aRow] = a4.z;
        As[aCol + 3][aRow] = a4.w;
        *(float4*)&Bs[loadRow][loadCol] =
            *(const float4*)&Mb[(size_t)(k0 + loadRow) * DIM + j0 + loadCol];
        __syncthreads();
#pragma unroll
        for (int kk = 0; kk < 8; kk++) {
            *(float4*)&ar[0] = *(float4*)&As[kk][ty * 4];
            *(float4*)&ar[4] = *(float4*)&As[kk][64 + ty * 4];
            *(float4*)&br[0] = *(float4*)&Bs[kk][tx * 4];
            *(float4*)&br[4] = *(float4*)&Bs[kk][64 + tx * 4];
#pragma unroll
            for (int ii = 0; ii < 8; ii++)
#pragma unroll
                for (int jj = 0; jj < 8; jj++)
                    acc[ii][jj] += ar[ii] * br[jj];
        }
        __syncthreads();
    }

    const float scale = 0.044194173824159216f;  // 1/sqrt(512)
#pragma unroll
    for (int ii = 0; ii < 8; ii++) {
        const int i = i0 + ((ii < 4) ? (ty * 4 + ii) : (64 + ty * 4 + ii - 4));
        float4 v0 = make_float4(acc[ii][0] * scale, acc[ii][1] * scale,
                                acc[ii][2] * scale, acc[ii][3] * scale);
        float4 v1 = make_float4(acc[ii][4] * scale, acc[ii][5] * scale,
                                acc[ii][6] * scale, acc[ii][7] * scale);
        *(float4*)&Xb[(size_t)i * DIM + j0 + tx * 4]      = v0;
        *(float4*)&Xb[(size_t)i * DIM + j0 + 64 + tx * 4] = v1;
    }
}

// ---------------------------------------------------------------------------
// Kernel C: in-place masked softmax; valid_len dtype chosen by detected flag.
// ---------------------------------------------------------------------------
__global__ __launch_bounds__(128) void softmax_kernel(float* __restrict__ X,
                                                      const void* __restrict__ vlen_raw) {
    const int row = blockIdx.x;
    const int q   = row & (SEQ - 1);
    long long L;
    if (g_vlen_is64) {
        L = ((const long long*)vlen_raw)[q];
    } else {
        L = (long long)((const int*)vlen_raw)[q];
    }
    float* xr = X + (size_t)row * DIM;

    const int t = threadIdx.x;
    const int j = t << 2;

    float4 v = *(float4*)&xr[j];
    float vals[4] = {v.x, v.y, v.z, v.w};
#pragma unroll
    for (int c = 0; c < 4; c++)
        if ((long long)(j + c) > L) vals[c] = -1000000.0f;

    __shared__ float red[4];
    const int lane = t & 31, warp = t >> 5;

    float m = fmaxf(fmaxf(vals[0], vals[1]), fmaxf(vals[2], vals[3]));
#pragma unroll
    for (int o = 16; o > 0; o >>= 1) m = fmaxf(m, __shfl_xor_sync(0xffffffffu, m, o));
    if (lane == 0) red[warp] = m;
    __syncthreads();
    m = fmaxf(fmaxf(red[0], red[1]), fmaxf(red[2], red[3]));
    __syncthreads();

    float e[4];
#pragma unroll
    for (int c = 0; c < 4; c++) e[c] = expf(vals[c] - m);

    float s = e[0] + e[1] + e[2] + e[3];
#pragma unroll
    for (int o = 16; o > 0; o >>= 1) s += __shfl_xor_sync(0xffffffffu, s, o);
    if (lane == 0) red[warp] = s;
    __syncthreads();
    s = red[0] + red[1] + red[2] + red[3];

    const float inv = 1.0f / s;
    float4 out = make_float4(e[0] * inv, e[1] * inv, e[2] * inv, e[3] * inv);
    *(float4*)&xr[j] = out;
}

// ---------------------------------------------------------------------------
// Launch: dict order (K, V, Q, valid_len); valid_len dtype runtime-detected.
// ---------------------------------------------------------------------------
extern "C" void kernel_launch(void* const* d_in, const int* in_sizes, int n_in,
                              void* d_out, int out_size) {
    const float* K = (const float*)d_in[0];
    const float* V = (const float*)d_in[1];
    const float* Q = (const float*)d_in[2];
    const void*  vlen = d_in[3];
    float* out = (float*)d_out;

    (void)in_sizes; (void)n_in; (void)out_size;

    detect_vlen_kernel<<<1, 256>>>((const unsigned long long*)vlen);
    ktv_kernel<<<dim3(DIM / 128, DIM / 128, BATCH), 256>>>(K, V);
    qm_kernel<<<dim3(DIM / 128, SEQ / 128, BATCH), 256>>>(Q, out);
    softmax_kernel<<<BATCH * SEQ, 128>>>(out, vlen);
}

// round 7
// speedup vs baseline: 1.4645x; 1.4645x over previous
#include <cuda_runtime.h>
#include <cuda_bf16.h>
#include <cstdint>

#define BATCH 8
#define SEQ   2048
#define DIM   512

// Scratch: M = K^T V, fp32 [b][i][j] : 8 MiB
__device__ float g_M[BATCH * DIM * DIM];
__device__ int g_vlen_is64;

// ---------------------------------------------------------------------------
// tf32 helpers (plain sm_103-safe: mma.sync + cvt.rna.tf32 are sm_80+ PTX)
// ---------------------------------------------------------------------------
__device__ __forceinline__ void split_tf32(float x, uint32_t& h, uint32_t& l) {
    asm("cvt.rna.tf32.f32 %0, %1;" : "=r"(h) : "f"(x));
    float r = x - __uint_as_float(h);
    asm("cvt.rna.tf32.f32 %0, %1;" : "=r"(l) : "f"(r));
}

__device__ __forceinline__ void mma_tf32(float* c, const uint32_t* a, const uint32_t* b) {
    asm volatile(
        "mma.sync.aligned.m16n8k8.row.col.f32.tf32.tf32.f32 "
        "{%0,%1,%2,%3}, {%4,%5,%6,%7}, {%8,%9}, {%0,%1,%2,%3};"
        : "+f"(c[0]), "+f"(c[1]), "+f"(c[2]), "+f"(c[3])
        : "r"(a[0]), "r"(a[1]), "r"(a[2]), "r"(a[3]), "r"(b[0]), "r"(b[1]));
}

// ---------------------------------------------------------------------------
// valid_len dtype detector (int64 vs int32) — proven in R4
// ---------------------------------------------------------------------------
__global__ void detect_vlen_kernel(const unsigned long long* __restrict__ v) {
    __shared__ int bad;
    if (threadIdx.x == 0) bad = 0;
    __syncthreads();
    for (int i = threadIdx.x; i < 1024; i += blockDim.x)
        if (v[i] >= 512ull) atomicOr(&bad, 1);
    __syncthreads();
    if (threadIdx.x == 0) g_vlen_is64 = bad ? 0 : 1;
}

// ---------------------------------------------------------------------------
// tf32 split-precision gemmA: M[i][j] = sum_s K[s][i] V[s][j]  (hh+hl+lh)
// Both operands k-major in gmem -> smem [32][132]. CTA 128x128, 8 warps of
// 64x32, K-chunk 32 (4 x k8 steps), double-buffered.
// (Under test this round: PASS clears this kernel, FAIL implicates it.)
// ---------------------------------------------------------------------------
#define A_FLOATS   4224                      // 32*132
#define B_FLOATS   4224
#define BUF_FLOATS (A_FLOATS + B_FLOATS)
#define DYN_SMEM   (2 * BUF_FLOATS * 4)      // 67584 bytes

__global__ __launch_bounds__(256, 1) void gemmA_tf32(const float* __restrict__ Kg,
                                                     const float* __restrict__ Vg) {
    constexpr int NCHUNK = SEQ / 32;
    extern __shared__ float sm[];

    const int t = threadIdx.x;
    const int wid = t >> 5, lane = t & 31;
    const int g = lane >> 2, q = lane & 3;
    const int mw = (wid >> 2) * 64;
    const int nw = (wid & 3) * 32;
    const int b = blockIdx.z;
    const int m0 = blockIdx.y * 128;
    const int n0 = blockIdx.x * 128;

    const float* Ab = Kg + (size_t)b * SEQ * DIM;
    const float* Bb = Vg + (size_t)b * SEQ * DIM;

    float acc[4][4][4] = {};
    float4 ar[4], br[4];

    const int krow = t >> 3, kcb = (t & 7) * 4;

#define LDG_AB(c) do {                                                         \
    const int k0_ = (c) * 32;                                                  \
    _Pragma("unroll")                                                          \
    for (int u = 0; u < 4; u++) {                                              \
        ar[u] = *(const float4*)&Ab[(size_t)(k0_ + krow) * DIM + m0 + kcb + u * 32]; \
        br[u] = *(const float4*)&Bb[(size_t)(k0_ + krow) * DIM + n0 + kcb + u * 32]; \
    }                                                                          \
} while (0)

#define STS_AB(buf) do {                                                       \
    float* As_ = sm + (buf) * BUF_FLOATS;                                      \
    float* Bs_ = As_ + A_FLOATS;                                               \
    _Pragma("unroll")                                                          \
    for (int u = 0; u < 4; u++) {                                              \
        *(float4*)&As_[krow * 132 + kcb + u * 32] = ar[u];                     \
        *(float4*)&Bs_[krow * 132 + kcb + u * 32] = br[u];                     \
    }                                                                          \
} while (0)

    LDG_AB(0);
    STS_AB(0);
    __syncthreads();

    for (int c = 0; c < NCHUNK; c++) {
        if (c + 1 < NCHUNK) LDG_AB(c + 1);

        const float* As = sm + (c & 1) * BUF_FLOATS;
        const float* Bs = As + A_FLOATS;

#pragma unroll
        for (int kk = 0; kk < 4; kk++) {
            uint32_t bh[8], bl[8];
#pragma unroll
            for (int nt = 0; nt < 4; nt++) {
                float x0 = Bs[(kk * 8 + q) * 132 + nw + nt * 8 + g];
                float x1 = Bs[(kk * 8 + q + 4) * 132 + nw + nt * 8 + g];
                split_tf32(x0, bh[nt * 2 + 0], bl[nt * 2 + 0]);
                split_tf32(x1, bh[nt * 2 + 1], bl[nt * 2 + 1]);
            }
            uint32_t ah[4][4], al[4][4];
#pragma unroll
            for (int mt = 0; mt < 4; mt++) {
                const float* r0 = &As[(kk * 8 + q) * 132 + mw + mt * 16 + g];
                const float* r1 = &As[(kk * 8 + q + 4) * 132 + mw + mt * 16 + g];
                split_tf32(r0[0], ah[mt][0], al[mt][0]);
                split_tf32(r0[8], ah[mt][1], al[mt][1]);
                split_tf32(r1[0], ah[mt][2], al[mt][2]);
                split_tf32(r1[8], ah[mt][3], al[mt][3]);
            }
#pragma unroll
            for (int mt = 0; mt < 4; mt++)
#pragma unroll
                for (int nt = 0; nt < 4; nt++)
                    mma_tf32(acc[mt][nt], ah[mt], &bh[nt * 2]);
#pragma unroll
            for (int mt = 0; mt < 4; mt++)
#pragma unroll
                for (int nt = 0; nt < 4; nt++)
                    mma_tf32(acc[mt][nt], ah[mt], &bl[nt * 2]);
#pragma unroll
            for (int mt = 0; mt < 4; mt++)
#pragma unroll
                for (int nt = 0; nt < 4; nt++)
                    mma_tf32(acc[mt][nt], al[mt], &bh[nt * 2]);
        }

        __syncthreads();
        if (c + 1 < NCHUNK) {
            STS_AB((c + 1) & 1);
            __syncthreads();
        }
    }

#pragma unroll
    for (int mt = 0; mt < 4; mt++) {
#pragma unroll
        for (int nt = 0; nt < 4; nt++) {
            const int m = m0 + mw + mt * 16 + g;
            const int n = n0 + nw + nt * 8 + 2 * q;
            float* dst = g_M + (size_t)b * DIM * DIM + (size_t)m * DIM + n;
            *(float2*)dst = make_float2(acc[mt][nt][0], acc[mt][nt][1]);
            *(float2*)(dst + 8 * DIM) = make_float2(acc[mt][nt][2], acc[mt][nt][3]);
        }
    }
#undef LDG_AB
#undef STS_AB
}

// ---------------------------------------------------------------------------
// PROVEN (R4) FFMA gemmB: X[b] = Q[b] @ g_M[b] * (1/sqrt(512)) -> d_out
// ---------------------------------------------------------------------------
__global__ __launch_bounds__(256) void qm_kernel(const float* __restrict__ Q,
                                                 float* __restrict__ X) {
    const int b  = blockIdx.z;
    const int i0 = blockIdx.y * 128;
    const int j0 = blockIdx.x * 128;
    const float* Qb = Q + (size_t)b * SEQ * DIM;
    const float* Mb = g_M + (size_t)b * DIM * DIM;
    float* Xb = X + (size_t)b * SEQ * DIM;

    __shared__ float As[8][132];
    __shared__ float Bs[8][128];

    const int t = threadIdx.x;
    const int aRow = t >> 1;
    const int aCol = (t & 1) << 2;
    const int loadRow = t >> 5;
    const int loadCol = (t & 31) << 2;
    const int tx = t & 15;
    const int ty = t >> 4;

    float acc[8][8] = {};
    float ar[8], br[8];

    for (int k0 = 0; k0 < DIM; k0 += 8) {
        float4 a4 = *(const float4*)&Qb[(size_t)(i0 + aRow) * DIM + k0 + aCol];
        As[aCol + 0][aRow] = a4.x;
        As[aCol + 1][aRow] = a4.y;
        As[aCol + 2][aRow] = a4.z;
        As[aCol + 3][aRow] = a4.w;
        *(float4*)&Bs[loadRow][loadCol] =
            *(const float4*)&Mb[(size_t)(k0 + loadRow) * DIM + j0 + loadCol];
        __syncthreads();
#pragma unroll
        for (int kk = 0; kk < 8; kk++) {
            *(float4*)&ar[0] = *(float4*)&As[kk][ty * 4];
            *(float4*)&ar[4] = *(float4*)&As[kk][64 + ty * 4];
            *(float4*)&br[0] = *(float4*)&Bs[kk][tx * 4];
            *(float4*)&br[4] = *(float4*)&Bs[kk][64 + tx * 4];
#pragma unroll
            for (int ii = 0; ii < 8; ii++)
#pragma unroll
                for (int jj = 0; jj < 8; jj++)
                    acc[ii][jj] += ar[ii] * br[jj];
        }
        __syncthreads();
    }

    const float scale = 0.044194173824159216f;  // 1/sqrt(512)
#pragma unroll
    for (int ii = 0; ii < 8; ii++) {
        const int i = i0 + ((ii < 4) ? (ty * 4 + ii) : (64 + ty * 4 + ii - 4));
        float4 v0 = make_float4(acc[ii][0] * scale, acc[ii][1] * scale,
                                acc[ii][2] * scale, acc[ii][3] * scale);
        float4 v1 = make_float4(acc[ii][4] * scale, acc[ii][5] * scale,
                                acc[ii][6] * scale, acc[ii][7] * scale);
        *(float4*)&Xb[(size_t)i * DIM + j0 + tx * 4]      = v0;
        *(float4*)&Xb[(size_t)i * DIM + j0 + 64 + tx * 4] = v1;
    }
}

// ---------------------------------------------------------------------------
// PROVEN (R4) masked softmax, dtype-flexible valid_len
// ---------------------------------------------------------------------------
__global__ __launch_bounds__(128) void softmax_kernel(float* __restrict__ X,
                                                      const void* __restrict__ vlen_raw) {
    const int row = blockIdx.x;
    const int qi = row & (SEQ - 1);
    long long L = g_vlen_is64 ? ((const long long*)vlen_raw)[qi]
                              : (long long)((const int*)vlen_raw)[qi];
    float* xr = X + (size_t)row * DIM;
    const int t = threadIdx.x;
    const int j = t << 2;

    float4 v = *(float4*)&xr[j];
    float vals[4] = {v.x, v.y, v.z, v.w};
#pragma unroll
    for (int c = 0; c < 4; c++)
        if ((long long)(j + c) > L) vals[c] = -1000000.0f;

    __shared__ float red[4];
    const int lane = t & 31, warp = t >> 5;

    float m = fmaxf(fmaxf(vals[0], vals[1]), fmaxf(vals[2], vals[3]));
#pragma unroll
    for (int o = 16; o > 0; o >>= 1) m = fmaxf(m, __shfl_xor_sync(0xffffffffu, m, o));
    if (lane == 0) red[warp] = m;
    __syncthreads();
    m = fmaxf(fmaxf(red[0], red[1]), fmaxf(red[2], red[3]));
    __syncthreads();

    float e[4];
#pragma unroll
    for (int c = 0; c < 4; c++) e[c] = expf(vals[c] - m);
    float s = e[0] + e[1] + e[2] + e[3];
#pragma unroll
    for (int o = 16; o > 0; o >>= 1) s += __shfl_xor_sync(0xffffffffu, s, o);
    if (lane == 0) red[warp] = s;
    __syncthreads();
    s = red[0] + red[1] + red[2] + red[3];

    const float inv = 1.0f / s;
    *(float4*)&xr[j] = make_float4(e[0] * inv, e[1] * inv, e[2] * inv, e[3] * inv);
}

// ---------------------------------------------------------------------------
// Launch (dict order K, V, Q, valid_len — proven R4)
// ---------------------------------------------------------------------------
extern "C" void kernel_launch(void* const* d_in, const int* in_sizes, int n_in,
                              void* d_out, int out_size) {
    const float* K = (const float*)d_in[0];
    const float* V = (const float*)d_in[1];
    const float* Q = (const float*)d_in[2];
    const void* vlen = d_in[3];
    float* out = (float*)d_out;
    (void)in_sizes; (void)n_in; (void)out_size;

    static bool attr_done = false;
    if (!attr_done) {
        cudaFuncSetAttribute(gemmA_tf32,
                             cudaFuncAttributeMaxDynamicSharedMemorySize, DYN_SMEM);
        attr_done = true;
    }

    detect_vlen_kernel<<<1, 256>>>((const unsigned long long*)vlen);

    // UNDER TEST: tf32 split gemmA -> g_M
    gemmA_tf32<<<dim3(4, 4, BATCH), 256, DYN_SMEM>>>(K, V);
    // PROVEN: FFMA gemmB -> logits, then masked softmax
    qm_kernel<<<dim3(DIM / 128, SEQ / 128, BATCH), 256>>>(Q, out);
    softmax_kernel<<<BATCH * SEQ, 128>>>(out, vlen);
}

// round 9
// speedup vs baseline: 1.5805x; 1.0792x over previous
#include <cuda_runtime.h>
#include <cuda_bf16.h>
#include <cstdint>

#define BATCH 8
#define SEQ   2048
#define DIM   512

// Scratch
__device__ float g_M[BATCH * DIM * DIM];    // M = K^T V   [b][i][j]   8 MiB
__device__ float g_Qt[BATCH * DIM * SEQ];   // Q^T         [b][i][q]  32 MiB
__device__ int g_vlen_is64;

// ---------------------------------------------------------------------------
// tf32 helpers
// ---------------------------------------------------------------------------
__device__ __forceinline__ void split_tf32(float x, uint32_t& h, uint32_t& l) {
    asm("cvt.rna.tf32.f32 %0, %1;" : "=r"(h) : "f"(x));
    float r = x - __uint_as_float(h);
    asm("cvt.rna.tf32.f32 %0, %1;" : "=r"(l) : "f"(r));
}

__device__ __forceinline__ void mma_tf32(float* c, const uint32_t* a, const uint32_t* b) {
    asm volatile(
        "mma.sync.aligned.m16n8k8.row.col.f32.tf32.tf32.f32 "
        "{%0,%1,%2,%3}, {%4,%5,%6,%7}, {%8,%9}, {%0,%1,%2,%3};"
        : "+f"(c[0]), "+f"(c[1]), "+f"(c[2]), "+f"(c[3])
        : "r"(a[0]), "r"(a[1]), "r"(a[2]), "r"(a[3]), "r"(b[0]), "r"(b[1]));
}

// ---------------------------------------------------------------------------
// valid_len dtype detector (int64 vs int32) — proven R4
// ---------------------------------------------------------------------------
__global__ void detect_vlen_kernel(const unsigned long long* __restrict__ v) {
    __shared__ int bad;
    if (threadIdx.x == 0) bad = 0;
    __syncthreads();
    for (int i = threadIdx.x; i < 1024; i += blockDim.x)
        if (v[i] >= 512ull) atomicOr(&bad, 1);
    __syncthreads();
    if (threadIdx.x == 0) g_vlen_is64 = bad ? 0 : 1;
}

// ---------------------------------------------------------------------------
// Q transpose: Q [B,SEQ,DIM] -> g_Qt [B,DIM,SEQ]  (32x32 smem tiles)
// ---------------------------------------------------------------------------
__global__ __launch_bounds__(256) void transposeQ_kernel(const float* __restrict__ Q) {
    __shared__ float tile[32][33];
    const int b = blockIdx.z;
    const int s0 = blockIdx.x * 32, d0 = blockIdx.y * 32;
    const int tx = threadIdx.x, ty = threadIdx.y;  // (32, 8)
    const float* src = Q + ((size_t)b * SEQ + s0) * DIM + d0;
#pragma unroll
    for (int i = 0; i < 4; i++)
        tile[ty + 8 * i][tx] = src[(size_t)(ty + 8 * i) * DIM + tx];
    __syncthreads();
    float* dst = g_Qt + ((size_t)b * DIM + d0) * SEQ + s0;
#pragma unroll
    for (int i = 0; i < 4; i++)
        dst[(size_t)(ty + 8 * i) * SEQ + tx] = tile[tx][ty + 8 * i];
}

// ===========================================================================
// Shared GEMM body (single static-smem buffer, register-prefetch) as a macro
// so gemmA/gemmB stay PLAIN non-template kernels (no dyn smem, no attributes).
// Computes D[m][n] = sum_k A[k][m]*B[k][n], 3 tf32 products (hh+hl+lh).
// CTA 128x128, 8 warps of 64x32, K-chunk 32 (4 x k8 steps).
// ===========================================================================
#define GEMM_BODY(NCHUNK, LDA, LDB, EPILOGUE)                                  \
    __shared__ float As[32 * 132];                                             \
    __shared__ float Bs[32 * 132];                                             \
    const int t = threadIdx.x;                                                 \
    const int wid = t >> 5, lane = t & 31;                                     \
    const int g = lane >> 2, q = lane & 3;                                     \
    const int mw = (wid >> 2) * 64;                                            \
    const int nw = (wid & 3) * 32;                                             \
    const int b = blockIdx.z;                                                  \
    const int m0 = blockIdx.y * 128;                                           \
    const int n0 = blockIdx.x * 128;                                           \
    float acc[4][4][4] = {};                                                   \
    float4 ar[4], br[4];                                                       \
    const int krow = t >> 3, kcb = (t & 7) * 4;                                \
    /* prologue load chunk 0 */                                                \
    _Pragma("unroll")                                                          \
    for (int u = 0; u < 4; u++) {                                              \
        ar[u] = *(const float4*)&Ab[(size_t)krow * (LDA) + m0 + kcb + u * 32]; \
        br[u] = *(const float4*)&Bb[(size_t)krow * (LDB) + n0 + kcb + u * 32]; \
    }                                                                          \
    _Pragma("unroll")                                                          \
    for (int u = 0; u < 4; u++) {                                              \
        *(float4*)&As[krow * 132 + kcb + u * 32] = ar[u];                      \
        *(float4*)&Bs[krow * 132 + kcb + u * 32] = br[u];                      \
    }                                                                          \
    __syncthreads();                                                           \
    for (int c = 0; c < (NCHUNK); c++) {                                       \
        if (c + 1 < (NCHUNK)) {                                                \
            const int kn = (c + 1) * 32;                                       \
            _Pragma("unroll")                                                  \
            for (int u = 0; u < 4; u++) {                                      \
                ar[u] = *(const float4*)&Ab[(size_t)(kn + krow) * (LDA) + m0 + kcb + u * 32]; \
                br[u] = *(const float4*)&Bb[(size_t)(kn + krow) * (LDB) + n0 + kcb + u * 32]; \
            }                                                                  \
        }                                                                      \
        _Pragma("unroll")                                                      \
        for (int kk = 0; kk < 4; kk++) {                                       \
            uint32_t bh[8], bl[8];                                             \
            _Pragma("unroll")                                                  \
            for (int nt = 0; nt < 4; nt++) {                                   \
                float x0 = Bs[(kk * 8 + q) * 132 + nw + nt * 8 + g];           \
                float x1 = Bs[(kk * 8 + q + 4) * 132 + nw + nt * 8 + g];       \
                split_tf32(x0, bh[nt * 2 + 0], bl[nt * 2 + 0]);                \
                split_tf32(x1, bh[nt * 2 + 1], bl[nt * 2 + 1]);                \
            }                                                                  \
            uint32_t ah[4][4], al[4][4];                                       \
            _Pragma("unroll")                                                  \
            for (int mt = 0; mt < 4; mt++) {                                   \
                const float* r0 = &As[(kk * 8 + q) * 132 + mw + mt * 16 + g];  \
                const float* r1 = &As[(kk * 8 + q + 4) * 132 + mw + mt * 16 + g]; \
                split_tf32(r0[0], ah[mt][0], al[mt][0]);                       \
                split_tf32(r0[8], ah[mt][1], al[mt][1]);                       \
                split_tf32(r1[0], ah[mt][2], al[mt][2]);                       \
                split_tf32(r1[8], ah[mt][3], al[mt][3]);                       \
            }                                                                  \
            _Pragma("unroll")                                                  \
            for (int mt = 0; mt < 4; mt++)                                     \
                _Pragma("unroll")                                              \
                for (int nt = 0; nt < 4; nt++)                                 \
                    mma_tf32(acc[mt][nt], ah[mt], &bh[nt * 2]);                \
            _Pragma("unroll")                                                  \
            for (int mt = 0; mt < 4; mt++)                                     \
                _Pragma("unroll")                                              \
                for (int nt = 0; nt < 4; nt++)                                 \
                    mma_tf32(acc[mt][nt], ah[mt], &bl[nt * 2]);                \
            _Pragma("unroll")                                                  \
            for (int mt = 0; mt < 4; mt++)                                     \
                _Pragma("unroll")                                              \
                for (int nt = 0; nt < 4; nt++)                                 \
                    mma_tf32(acc[mt][nt], al[mt], &bh[nt * 2]);                \
        }                                                                      \
        __syncthreads();                                                       \
        if (c + 1 < (NCHUNK)) {                                                \
            _Pragma("unroll")                                                  \
            for (int u = 0; u < 4; u++) {                                      \
                *(float4*)&As[krow * 132 + kcb + u * 32] = ar[u];              \
                *(float4*)&Bs[krow * 132 + kcb + u * 32] = br[u];              \
            }                                                                  \
            __syncthreads();                                                   \
        }                                                                      \
    }                                                                          \
    _Pragma("unroll")                                                          \
    for (int mt = 0; mt < 4; mt++) {                                           \
        _Pragma("unroll")                                                      \
        for (int nt = 0; nt < 4; nt++) {                                       \
            const int m = m0 + mw + mt * 16 + g;                               \
            const int n = n0 + nw + nt * 8 + 2 * q;                            \
            EPILOGUE                                                           \
        }                                                                      \
    }

// ---------------------------------------------------------------------------
// gemmA: M[i][j] = sum_s K[s][i] V[s][j]    (k-major x k-major, K=2048)
// ---------------------------------------------------------------------------
__global__ __launch_bounds__(256, 1) void gemmA_tf32(const float* __restrict__ Kg,
                                                     const float* __restrict__ Vg) {
    const float* Ab = Kg + (size_t)blockIdx.z * SEQ * DIM;
    const float* Bb = Vg + (size_t)blockIdx.z * SEQ * DIM;
    GEMM_BODY(SEQ / 32, DIM, DIM, {
        float* dst = g_M + (size_t)b * DIM * DIM + (size_t)m * DIM + n;
        *(float2*)dst = make_float2(acc[mt][nt][0], acc[mt][nt][1]);
        *(float2*)(dst + 8 * DIM) = make_float2(acc[mt][nt][2], acc[mt][nt][3]);
    })
}

// ---------------------------------------------------------------------------
// gemmB: X[q][j] = sum_i Qt[i][q] M[i][j] / sqrt(512)   (K=512)
// ---------------------------------------------------------------------------
__global__ __launch_bounds__(256, 1) void gemmB_tf32(float* __restrict__ Og) {
    const float* Ab = g_Qt + (size_t)blockIdx.z * DIM * SEQ;
    const float* Bb = g_M + (size_t)blockIdx.z * DIM * DIM;
    GEMM_BODY(DIM / 32, SEQ, DIM, {
        const float sc = 0.044194173824159216f; /* 1/sqrt(512) */
        float* dst = Og + ((size_t)b * SEQ + m) * DIM + n;
        *(float2*)dst = make_float2(acc[mt][nt][0] * sc, acc[mt][nt][1] * sc);
        *(float2*)(dst + 8 * DIM) =
            make_float2(acc[mt][nt][2] * sc, acc[mt][nt][3] * sc);
    })
}

// ---------------------------------------------------------------------------
// PROVEN (R4) masked softmax, dtype-flexible valid_len
// ---------------------------------------------------------------------------
__global__ __launch_bounds__(128) void softmax_kernel(float* __restrict__ X,
                                                      const void* __restrict__ vlen_raw) {
    const int row = blockIdx.x;
    const int qi = row & (SEQ - 1);
    long long L = g_vlen_is64 ? ((const long long*)vlen_raw)[qi]
                              : (long long)((const int*)vlen_raw)[qi];
    float* xr = X + (size_t)row * DIM;
    const int t = threadIdx.x;
    const int j = t << 2;

    float4 v = *(float4*)&xr[j];
    float vals[4] = {v.x, v.y, v.z, v.w};
#pragma unroll
    for (int c = 0; c < 4; c++)
        if ((long long)(j + c) > L) vals[c] = -1000000.0f;

    __shared__ float red[4];
    const int lane = t & 31, warp = t >> 5;

    float m = fmaxf(fmaxf(vals[0], vals[1]), fmaxf(vals[2], vals[3]));
#pragma unroll
    for (int o = 16; o > 0; o >>= 1) m = fmaxf(m, __shfl_xor_sync(0xffffffffu, m, o));
    if (lane == 0) red[warp] = m;
    __syncthreads();
    m = fmaxf(fmaxf(red[0], red[1]), fmaxf(red[2], red[3]));
    __syncthreads();

    float e[4];
#pragma unroll
    for (int c = 0; c < 4; c++) e[c] = expf(vals[c] - m);
    float s = e[0] + e[1] + e[2] + e[3];
#pragma unroll
    for (int o = 16; o > 0; o >>= 1) s += __shfl_xor_sync(0xffffffffu, s, o);
    if (lane == 0) red[warp] = s;
    __syncthreads();
    s = red[0] + red[1] + red[2] + red[3];

    const float inv = 1.0f / s;
    *(float4*)&xr[j] = make_float4(e[0] * inv, e[1] * inv, e[2] * inv, e[3] * inv);
}

// ---------------------------------------------------------------------------
// Launch (dict order K, V, Q, valid_len — proven R4). No dynamic smem, no
// attributes, no templates: the R6/R8 silent-launch-failure class is gone.
// ---------------------------------------------------------------------------
extern "C" void kernel_launch(void* const* d_in, const int* in_sizes, int n_in,
                              void* d_out, int out_size) {
    const float* K = (const float*)d_in[0];
    const float* V = (const float*)d_in[1];
    const float* Q = (const float*)d_in[2];
    const void* vlen = d_in[3];
    float* out = (float*)d_out;
    (void)in_sizes; (void)n_in; (void)out_size;

    detect_vlen_kernel<<<1, 256>>>((const unsigned long long*)vlen);
    transposeQ_kernel<<<dim3(SEQ / 32, DIM / 32, BATCH), dim3(32, 8)>>>(Q);

    gemmA_tf32<<<dim3(4, 4, BATCH), 256>>>(K, V);
    gemmB_tf32<<<dim3(4, 16, BATCH), 256>>>(out);

    softmax_kernel<<<BATCH * SEQ, 128>>>(out, vlen);
}